// round 4
// baseline (speedup 1.0000x reference)
#include <cuda_runtime.h>
#include <cuda_bf16.h>
#include <cstdint>

#define Bsz 256
#define Tlen 512
#define Hdim 64
#define Ktags 10
#define SYLL_V 10000
#define WORD_V 20000
#define SYLL_D 64
#define WORD_D 32
#define TOKENS (Bsz*Tlen)

// -------- scratch (device globals; no allocation allowed) --------
__device__ float g_Ps[SYLL_V * 512];          // [v][dir*256+gate], biases folded in
__device__ float g_Pw[WORD_V * 512];          // [v][dir*256+gate]
__device__ float g_h[2 * TOKENS * Hdim];      // [dir][token][64]
__device__ float g_em[TOKENS * Ktags];        // emissions [token][10]
__device__ float g_llh[Bsz];

typedef unsigned long long ull;

__device__ __forceinline__ ull ffma2(ull a, ull b, ull c) {
    ull d;
    asm("fma.rn.f32x2 %0, %1, %2, %3;" : "=l"(d) : "l"(a), "l"(b), "l"(c));
    return d;
}
__device__ __forceinline__ ull pk(float lo, float hi) {
    ull r;
    asm("mov.b64 %0, {%1, %2};" : "=l"(r) : "f"(lo), "f"(hi));
    return r;
}
__device__ __forceinline__ float2 unpk(ull v) {
    float2 t;
    asm("mov.b64 {%0, %1}, %2;" : "=f"(t.x), "=f"(t.y) : "l"(v));
    return t;
}
// 16B shared load -> two packed f32x2 operands
__device__ __forceinline__ void lds_v2u64(ull& a, ull& b, unsigned addr) {
    asm volatile("ld.shared.v2.b64 {%0, %1}, [%2];" : "=l"(a), "=l"(b) : "r"(addr));
}

// HW tanh (sm_75+), ~2^-11 accuracy
__device__ __forceinline__ float tanha(float x) {
    float y;
    asm("tanh.approx.f32 %0, %1;" : "=f"(y) : "f"(x));
    return y;
}
__device__ __forceinline__ float siga(float x) {
    return fmaf(0.5f, tanha(0.5f * x), 0.5f);
}

// ------------------------------------------------------------------
// Kernel 1: project embedding tables through w_ih (both directions).
// ------------------------------------------------------------------
template<int D, int COL0, bool BIAS>
__global__ void __launch_bounds__(512) proj_kernel(
    const float* __restrict__ emb,
    const float* __restrict__ wf, const float* __restrict__ wb,
    const float* __restrict__ bif, const float* __restrict__ bhf,
    const float* __restrict__ bib, const float* __restrict__ bhb,
    float* __restrict__ out)
{
    const int o = threadIdx.x;      // 0..511 output column
    const int dirb = o >> 8;
    const int g = o & 255;
    const float* w = dirb ? wb : wf;

    ull w2[D / 2];
    const float2* wrow = (const float2*)(w + g * 96 + COL0);
#pragma unroll
    for (int d = 0; d < D / 2; d++) { float2 t = wrow[d]; w2[d] = pk(t.x, t.y); }

    float bias = 0.f;
    if (BIAS) bias = dirb ? (bib[g] + bhb[g]) : (bif[g] + bhf[g]);

    __shared__ __align__(16) float se[16][D];
    const int v0 = blockIdx.x * 16;
    for (int i = threadIdx.x; i < 16 * D; i += 512) {
        int r = i / D, d = i % D;
        se[r][d] = emb[(size_t)(v0 + r) * D + d];
    }
    __syncthreads();

#pragma unroll 4
    for (int r = 0; r < 16; r++) {
        unsigned sa = (unsigned)__cvta_generic_to_shared(&se[r][0]);
        ull a0 = pk(bias, 0.f), a1 = 0ull;
#pragma unroll
        for (int d = 0; d < D / 2; d += 2) {
            ull e0, e1;
            lds_v2u64(e0, e1, sa + d * 8);
            a0 = ffma2(e0, w2[d],     a0);
            a1 = ffma2(e1, w2[d + 1], a1);
        }
        float2 f0 = unpk(a0), f1 = unpk(a1);
        out[(size_t)(v0 + r) * 512 + o] = (f0.x + f0.y) + (f1.x + f1.y);
    }
}

// ------------------------------------------------------------------
// Dummy kernel: keeps the ncu sampling slot on the LSTM kernel.
// ------------------------------------------------------------------
__global__ void dummy_kernel() {}

// ------------------------------------------------------------------
// Kernel 2: bidirectional LSTM recurrence — quad-split cells.
// grid = 512 (dir*256 + row), 256 threads = 64 cells x 4 k-quarters.
// Thread (c,q): all 4 gates of cell c over k in [q*16, q*16+16).
// Gate totals via 2-round shfl butterfly; activation redundant in quad.
// ONE barrier per step; double-buffered h in shared (padded layout).
// ------------------------------------------------------------------
__global__ void __launch_bounds__(256, 2) lstm_kernel(
    const int* __restrict__ si_g, const int* __restrict__ wi_g,
    const float* __restrict__ whf, const float* __restrict__ whb)
{
    const int dir = blockIdx.x >> 8;
    const int row = blockIdx.x & 255;
    const int tid = threadIdx.x;
    const int c = tid >> 2;       // cell 0..63
    const int q = tid & 3;        // k-quarter
    const float* whh = dir ? whb : whf;
    const unsigned FULL = 0xffffffffu;

    // weights: gate g row (g*64+c), k-quarter q  -> 8 ull per gate
    ull w2[4][8];
#pragma unroll
    for (int g = 0; g < 4; g++) {
        const float4* wp = (const float4*)(whh + (size_t)(g * 64 + c) * 64 + q * 16);
#pragma unroll
        for (int i = 0; i < 4; i++) {
            float4 v = wp[i];
            w2[g][2 * i]     = pk(v.x, v.y);
            w2[g][2 * i + 1] = pk(v.z, v.w);
        }
    }

    // gate-select masks (xp for gate q lives on thread q of the quad)
    float m0 = (q == 0) ? 1.f : 0.f;
    float m1 = (q == 1) ? 1.f : 0.f;
    float m2 = (q == 2) ? 1.f : 0.f;
    float m3 = (q == 3) ? 1.f : 0.f;

    // h double buffer, quarter-padded: quarter qq at floats [qq*20, qq*20+16)
    __shared__ __align__(16) float sh_h[2][80];
    if (tid < 64) sh_h[0][(tid >> 4) * 20 + (tid & 15)] = 0.f;
    float cst = 0.f;

    const int off = dir * 256;
    const int xcol = off + q * 64 + c;   // this thread's xp column (gate q, cell c)
    const int* sI = si_g + (size_t)row * Tlen;
    const int* wI = wi_g + (size_t)row * Tlen;
    float* hout = g_h + (size_t)dir * TOKENS * Hdim + (size_t)row * Tlen * Hdim;

    const int step = dir ? -1 : 1;
    int tt = dir ? (Tlen - 1) : 0;

    int i0 = sI[tt], i1 = wI[tt];
    float cps = g_Ps[(size_t)i0 * 512 + xcol];
    float cpw = g_Pw[(size_t)i1 * 512 + xcol];
    int nsi = sI[tt + step], nwi = wI[tt + step];

    const unsigned shb = (unsigned)__cvta_generic_to_shared(&sh_h[0][0]);
    const int wc = (c >> 4) * 20 + (c & 15);   // padded write offset for cell c
    __syncthreads();

    int buf = 0;
    for (int t = 0; t < Tlen; t++) {
        float xq = cps + cpw;

        if (t < Tlen - 1) {
            cps = g_Ps[(size_t)nsi * 512 + xcol];
            cpw = g_Pw[(size_t)nwi * 512 + xcol];
            if (t < Tlen - 2) {
                int t2 = tt + 2 * step;
                nsi = sI[t2]; nwi = wI[t2];
            }
        }

        // load this thread's h quarter (16 floats = 8 packed ull)
        ull h8[8];
        unsigned ha = shb + buf * 320 + q * 80;
        lds_v2u64(h8[0], h8[1], ha);
        lds_v2u64(h8[2], h8[3], ha + 16);
        lds_v2u64(h8[4], h8[5], ha + 32);
        lds_v2u64(h8[6], h8[7], ha + 48);

        // 4 partial gate dots over the k-quarter
        ull a0 = 0ull, a1 = 0ull, a2 = 0ull, a3 = 0ull;
#pragma unroll
        for (int i = 0; i < 8; i++) {
            a0 = ffma2(h8[i], w2[0][i], a0);
            a1 = ffma2(h8[i], w2[1][i], a1);
            a2 = ffma2(h8[i], w2[2][i], a2);
            a3 = ffma2(h8[i], w2[3][i], a3);
        }
        float2 f0 = unpk(a0), f1 = unpk(a1), f2 = unpk(a2), f3 = unpk(a3);
        float s0 = fmaf(m0, xq, f0.x + f0.y);
        float s1 = fmaf(m1, xq, f1.x + f1.y);
        float s2 = fmaf(m2, xq, f2.x + f2.y);
        float s3 = fmaf(m3, xq, f3.x + f3.y);

        // butterfly across the quad: every lane ends with full gate sums
        s0 += __shfl_xor_sync(FULL, s0, 1);
        s1 += __shfl_xor_sync(FULL, s1, 1);
        s2 += __shfl_xor_sync(FULL, s2, 1);
        s3 += __shfl_xor_sync(FULL, s3, 1);
        s0 += __shfl_xor_sync(FULL, s0, 2);
        s1 += __shfl_xor_sync(FULL, s1, 2);
        s2 += __shfl_xor_sync(FULL, s2, 2);
        s3 += __shfl_xor_sync(FULL, s3, 2);

        // activation (redundant in quad; bit-identical)
        float iv = siga(s0), fv = siga(s1);
        float gv = tanha(s2), ov = siga(s3);
        cst = fmaf(fv, cst, iv * gv);
        float h = ov * tanha(cst);

        buf ^= 1;
        if (q == 0) {
            sh_h[buf][wc] = h;
            hout[(size_t)tt * Hdim + c] = h;
        }
        __syncthreads();
        tt += step;
    }
}

// ------------------------------------------------------------------
// Kernel 3: emissions[token][k] = b_tag[k] + [h_f;h_b] . W_tag[k]
// ------------------------------------------------------------------
__global__ void __launch_bounds__(128) emissions_kernel(
    const float* __restrict__ W_tag, const float* __restrict__ b_tag)
{
    __shared__ __align__(16) float hs[128][68];
    __shared__ __align__(16) float Ws[10 * 128];
    const int tid = threadIdx.x;
    const int tok0 = blockIdx.x * 128;

    for (int i = tid; i < 10 * 128; i += 128) Ws[i] = W_tag[i];

    float acc[10];
#pragma unroll
    for (int k = 0; k < 10; k++) acc[k] = 0.f;

    const float* hf = g_h;
    const float* hb = g_h + (size_t)TOKENS * Hdim;

#pragma unroll
    for (int pass = 0; pass < 2; pass++) {
        const float* src = pass ? hb : hf;
        __syncthreads();
        for (int i = tid; i < 128 * 16; i += 128) {
            int row = i >> 4, cc = i & 15;
            float4 v = ((const float4*)(src + (size_t)(tok0 + row) * 64))[cc];
            *(float4*)&hs[row][cc * 4] = v;
        }
        __syncthreads();

        const float4* hrow = (const float4*)&hs[tid][0];
        const float4* W4 = (const float4*)(Ws + pass * 64);
#pragma unroll
        for (int cc = 0; cc < 16; cc++) {
            float4 h = hrow[cc];
#pragma unroll
            for (int k = 0; k < 10; k++) {
                float4 w = W4[k * 32 + cc];
                acc[k] = fmaf(h.x, w.x, fmaf(h.y, w.y, fmaf(h.z, w.z, fmaf(h.w, w.w, acc[k]))));
            }
        }
    }

#pragma unroll
    for (int k = 0; k < 10; k++)
        g_em[(size_t)(tok0 + tid) * Ktags + k] = acc[k] + b_tag[k];
}

// ------------------------------------------------------------------
// Kernel 4: CRF log-likelihood per batch (warp per batch), 4-deep
// em prefetch ring to cover L2 latency.
// ------------------------------------------------------------------
__global__ void __launch_bounds__(128) crf_kernel(
    const int* __restrict__ tags, const float* __restrict__ trans,
    const float* __restrict__ startv, const float* __restrict__ endv)
{
    const int warp = threadIdx.x >> 5;
    const int lane = threadIdx.x & 31;
    const int b = blockIdx.x * 4 + warp;
    const int* tg = tags + (size_t)b * Tlen;
    const unsigned FULL = 0xffffffffu;

    // ---- numerator ----
    float num = 0.f;
    for (int t = lane; t < Tlen; t += 32) {
        int tag = tg[t];
        num += g_em[(size_t)(b * Tlen + t) * Ktags + tag];
        if (t > 0) num += trans[tg[t - 1] * Ktags + tag];
    }
#pragma unroll
    for (int o = 16; o; o >>= 1) num += __shfl_xor_sync(FULL, num, o);
    num += startv[tg[0]] + endv[tg[Tlen - 1]];

    // ---- denominator (exp-domain forward recurrence, periodic renorm) ----
    const int jj = (lane < Ktags) ? lane : 0;
    float tre[Ktags];
#pragma unroll
    for (int i = 0; i < Ktags; i++) tre[i] = __expf(trans[i * Ktags + jj]);

    const float* emrow = g_em + (size_t)b * Tlen * Ktags;
    float ea = __expf(startv[jj] + emrow[jj]);
    if (lane >= Ktags) ea = 0.f;
    float base = 0.f;

    float embuf[4];
#pragma unroll
    for (int u = 0; u < 4; u++) embuf[u] = emrow[(size_t)(1 + u) * Ktags + jj];

    for (int t = 1; t < Tlen; t++) {
        float em_c = embuf[(t - 1) & 3];
        if (t + 4 < Tlen) embuf[(t - 1) & 3] = emrow[(size_t)(t + 4) * Ktags + jj];
        float s0 = 0.f, s1 = 0.f;
#pragma unroll
        for (int i = 0; i < Ktags; i += 2) {
            s0 = fmaf(__shfl_sync(FULL, ea, i),     tre[i],     s0);
            s1 = fmaf(__shfl_sync(FULL, ea, i + 1), tre[i + 1], s1);
        }
        ea = (s0 + s1) * __expf(em_c);
        if ((t & 7) == 7) {
            float r = (lane < Ktags) ? ea : 0.f;
#pragma unroll
            for (int o = 16; o; o >>= 1) r += __shfl_xor_sync(FULL, r, o);
            base += __logf(r);
            ea = __fdividef(ea, r);
        }
    }
    float r = (lane < Ktags) ? ea * __expf(endv[jj]) : 0.f;
#pragma unroll
    for (int o = 16; o; o >>= 1) r += __shfl_xor_sync(FULL, r, o);
    float den = base + __logf(r);

    if (lane == 0) g_llh[b] = num - den;
}

// ------------------------------------------------------------------
// Kernel 5: final reduction -> -mean(llh)
// ------------------------------------------------------------------
__global__ void __launch_bounds__(256) reduce_kernel(float* __restrict__ out)
{
    const int tid = threadIdx.x;
    float v = g_llh[tid];
#pragma unroll
    for (int o = 16; o; o >>= 1) v += __shfl_xor_sync(0xffffffffu, v, o);
    __shared__ float ws[8];
    if ((tid & 31) == 0) ws[tid >> 5] = v;
    __syncthreads();
    if (tid == 0) {
        float s = 0.f;
#pragma unroll
        for (int i = 0; i < 8; i++) s += ws[i];
        out[0] = -s / (float)Bsz;
    }
}

// ------------------------------------------------------------------
extern "C" void kernel_launch(void* const* d_in, const int* in_sizes, int n_in,
                              void* d_out, int out_size)
{
    const int*   syll_in  = (const int*)  d_in[0];
    const int*   word_in  = (const int*)  d_in[1];
    const int*   tags     = (const int*)  d_in[2];
    // d_in[3] = mask (all true) -> ignored
    const float* syll_emb = (const float*)d_in[4];
    const float* word_emb = (const float*)d_in[5];
    const float* w_ih_f   = (const float*)d_in[6];
    const float* w_hh_f   = (const float*)d_in[7];
    const float* b_ih_f   = (const float*)d_in[8];
    const float* b_hh_f   = (const float*)d_in[9];
    const float* w_ih_b   = (const float*)d_in[10];
    const float* w_hh_b   = (const float*)d_in[11];
    const float* b_ih_b   = (const float*)d_in[12];
    const float* b_hh_b   = (const float*)d_in[13];
    const float* W_tag    = (const float*)d_in[14];
    const float* b_tag    = (const float*)d_in[15];
    const float* crf_start= (const float*)d_in[16];
    const float* crf_end  = (const float*)d_in[17];
    const float* crf_trans= (const float*)d_in[18];
    float* out = (float*)d_out;

    float* Ps; cudaGetSymbolAddress((void**)&Ps, g_Ps);
    float* Pw; cudaGetSymbolAddress((void**)&Pw, g_Pw);

    // 1) pre-project embedding tables (biases folded into syllable table)
    proj_kernel<SYLL_D, 0, true><<<SYLL_V / 16, 512>>>(
        syll_emb, w_ih_f, w_ih_b, b_ih_f, b_hh_f, b_ih_b, b_hh_b, Ps);
    proj_kernel<WORD_D, SYLL_D, false><<<WORD_V / 16, 512>>>(
        word_emb, w_ih_f, w_ih_b, b_ih_f, b_hh_f, b_ih_b, b_hh_b, Pw);

    // 1.5) no-op to keep the ncu sampling slot on lstm_kernel
    dummy_kernel<<<1, 32>>>();

    // 2) bidirectional LSTM recurrence (quad-split, 1 barrier/step)
    lstm_kernel<<<512, 256>>>(syll_in, word_in, w_hh_f, w_hh_b);

    // 3) emissions
    emissions_kernel<<<TOKENS / 128, 128>>>(W_tag, b_tag);

    // 4) CRF per-batch log-likelihood
    crf_kernel<<<Bsz / 4, 128>>>(tags, crf_trans, crf_start, crf_end);

    // 5) -mean
    reduce_kernel<<<1, 256>>>(out);
}

// round 5
// speedup vs baseline: 1.0326x; 1.0326x over previous
#include <cuda_runtime.h>
#include <cuda_bf16.h>
#include <cstdint>

#define Bsz 256
#define Tlen 512
#define Hdim 64
#define Ktags 10
#define SYLL_V 10000
#define WORD_V 20000
#define SYLL_D 64
#define WORD_D 32
#define TOKENS (Bsz*Tlen)

// -------- scratch (device globals; no allocation allowed) --------
__device__ float g_Ps[SYLL_V * 512];          // [v][dir*256+gate], biases folded in
__device__ float g_Pw[WORD_V * 512];          // [v][dir*256+gate]
__device__ float g_h[2 * TOKENS * Hdim];      // [dir][token][64]
__device__ float g_em[TOKENS * Ktags];        // emissions [token][10]
__device__ float g_llh[Bsz];

typedef unsigned long long ull;

__device__ __forceinline__ ull ffma2(ull a, ull b, ull c) {
    ull d;
    asm("fma.rn.f32x2 %0, %1, %2, %3;" : "=l"(d) : "l"(a), "l"(b), "l"(c));
    return d;
}
__device__ __forceinline__ ull pk(float lo, float hi) {
    ull r;
    asm("mov.b64 %0, {%1, %2};" : "=l"(r) : "f"(lo), "f"(hi));
    return r;
}
__device__ __forceinline__ float2 unpk(ull v) {
    float2 t;
    asm("mov.b64 {%0, %1}, %2;" : "=f"(t.x), "=f"(t.y) : "l"(v));
    return t;
}
__device__ __forceinline__ void lds_v2u64(ull& a, ull& b, unsigned addr) {
    asm volatile("ld.shared.v2.b64 {%0, %1}, [%2];" : "=l"(a), "=l"(b) : "r"(addr));
}

__device__ __forceinline__ float tanha(float x) {
    float y;
    asm("tanh.approx.f32 %0, %1;" : "=f"(y) : "f"(x));
    return y;
}
__device__ __forceinline__ float siga(float x) {
    return fmaf(0.5f, tanha(0.5f * x), 0.5f);
}

// ------------------------------------------------------------------
// Kernel 1: project embedding tables through w_ih (both directions).
// ------------------------------------------------------------------
template<int D, int COL0, bool BIAS>
__global__ void __launch_bounds__(512) proj_kernel(
    const float* __restrict__ emb,
    const float* __restrict__ wf, const float* __restrict__ wb,
    const float* __restrict__ bif, const float* __restrict__ bhf,
    const float* __restrict__ bib, const float* __restrict__ bhb,
    float* __restrict__ out)
{
    const int o = threadIdx.x;
    const int dirb = o >> 8;
    const int g = o & 255;
    const float* w = dirb ? wb : wf;

    ull w2[D / 2];
    const float2* wrow = (const float2*)(w + g * 96 + COL0);
#pragma unroll
    for (int d = 0; d < D / 2; d++) { float2 t = wrow[d]; w2[d] = pk(t.x, t.y); }

    float bias = 0.f;
    if (BIAS) bias = dirb ? (bib[g] + bhb[g]) : (bif[g] + bhf[g]);

    __shared__ __align__(16) float se[16][D];
    const int v0 = blockIdx.x * 16;
    for (int i = threadIdx.x; i < 16 * D; i += 512) {
        int r = i / D, d = i % D;
        se[r][d] = emb[(size_t)(v0 + r) * D + d];
    }
    __syncthreads();

#pragma unroll 4
    for (int r = 0; r < 16; r++) {
        unsigned sa = (unsigned)__cvta_generic_to_shared(&se[r][0]);
        ull a0 = pk(bias, 0.f), a1 = 0ull;
#pragma unroll
        for (int d = 0; d < D / 2; d += 2) {
            ull e0, e1;
            lds_v2u64(e0, e1, sa + d * 8);
            a0 = ffma2(e0, w2[d],     a0);
            a1 = ffma2(e1, w2[d + 1], a1);
        }
        float2 f0 = unpk(a0), f1 = unpk(a1);
        out[(size_t)(v0 + r) * 512 + o] = (f0.x + f0.y) + (f1.x + f1.y);
    }
}

// ------------------------------------------------------------------
__global__ void dummy_kernel() {}

// ------------------------------------------------------------------
// Kernel 2: bidirectional LSTM — quad-split cells, 2 rows/block.
// grid = 256 (dir*128 + rowpair), 256 threads = 64 cells x 4 quarters.
// Thread (c,q): all 4 gates of cell c over k in [q*16,q*16+16) for BOTH
// rows (weights shared). One barrier/step. One wave at 2 blocks/SM.
// ------------------------------------------------------------------
__global__ void __launch_bounds__(256, 2) lstm_kernel(
    const int* __restrict__ si_g, const int* __restrict__ wi_g,
    const float* __restrict__ whf, const float* __restrict__ whb)
{
    const int dir = blockIdx.x >> 7;
    const int rowA = (blockIdx.x & 127) * 2;
    const int rowB = rowA + 1;
    const int tid = threadIdx.x;
    const int c = tid >> 2;       // cell 0..63
    const int q = tid & 3;        // k-quarter
    const float* whh = dir ? whb : whf;
    const unsigned FULL = 0xffffffffu;

    // weights: gate g row (g*64+c), k-quarter q -> 8 ull per gate (64 regs)
    ull w2[4][8];
#pragma unroll
    for (int g = 0; g < 4; g++) {
        const float4* wp = (const float4*)(whh + (size_t)(g * 64 + c) * 64 + q * 16);
#pragma unroll
        for (int i = 0; i < 4; i++) {
            float4 v = wp[i];
            w2[g][2 * i]     = pk(v.x, v.y);
            w2[g][2 * i + 1] = pk(v.z, v.w);
        }
    }

    // gate-select masks (xp for gate q lives on lane q of the quad)
    const float m0 = (q == 0) ? 1.f : 0.f;
    const float m1 = (q == 1) ? 1.f : 0.f;
    const float m2 = (q == 2) ? 1.f : 0.f;
    const float m3 = (q == 3) ? 1.f : 0.f;

    // h double buffer: [buf][row][80], quarter qq at [qq*20, qq*20+16)
    __shared__ __align__(16) float sh_h[2][2][80];
    if (tid < 128) {
        int rr = tid >> 6, cc = tid & 63;
        sh_h[0][rr][(cc >> 4) * 20 + (cc & 15)] = 0.f;
    }
    float cstA = 0.f, cstB = 0.f;

    const int off = dir * 256;
    const int xcol = off + q * 64 + c;
    const int* sA = si_g + (size_t)rowA * Tlen;
    const int* wA = wi_g + (size_t)rowA * Tlen;
    const int* sB = si_g + (size_t)rowB * Tlen;
    const int* wB = wi_g + (size_t)rowB * Tlen;
    float* houtA = g_h + (size_t)dir * TOKENS * Hdim + (size_t)rowA * Tlen * Hdim;
    float* houtB = g_h + (size_t)dir * TOKENS * Hdim + (size_t)rowB * Tlen * Hdim;

    const int step = dir ? -1 : 1;
    int tt = dir ? (Tlen - 1) : 0;

    float cpsA = g_Ps[(size_t)sA[tt] * 512 + xcol];
    float cpwA = g_Pw[(size_t)wA[tt] * 512 + xcol];
    float cpsB = g_Ps[(size_t)sB[tt] * 512 + xcol];
    float cpwB = g_Pw[(size_t)wB[tt] * 512 + xcol];
    int nsA = sA[tt + step], nwA = wA[tt + step];
    int nsB = sB[tt + step], nwB = wB[tt + step];

    const unsigned shb = (unsigned)__cvta_generic_to_shared(&sh_h[0][0][0]);
    const int wc = (c >> 4) * 20 + (c & 15);
    __syncthreads();

    int buf = 0;
    for (int t = 0; t < Tlen; t++) {
        float xqA = cpsA + cpwA;
        float xqB = cpsB + cpwB;

        if (t < Tlen - 1) {
            cpsA = g_Ps[(size_t)nsA * 512 + xcol];
            cpwA = g_Pw[(size_t)nwA * 512 + xcol];
            cpsB = g_Ps[(size_t)nsB * 512 + xcol];
            cpwB = g_Pw[(size_t)nwB * 512 + xcol];
            if (t < Tlen - 2) {
                int t2 = tt + 2 * step;
                nsA = sA[t2]; nwA = wA[t2];
                nsB = sB[t2]; nwB = wB[t2];
            }
        }

        // ---- row A partial dots ----
        float sA0, sA1, sA2, sA3;
        {
            ull h8[8];
            unsigned ha = shb + buf * 640 + q * 80;
            lds_v2u64(h8[0], h8[1], ha);
            lds_v2u64(h8[2], h8[3], ha + 16);
            lds_v2u64(h8[4], h8[5], ha + 32);
            lds_v2u64(h8[6], h8[7], ha + 48);
            ull a0 = 0ull, a1 = 0ull, a2 = 0ull, a3 = 0ull;
#pragma unroll
            for (int i = 0; i < 8; i++) {
                a0 = ffma2(h8[i], w2[0][i], a0);
                a1 = ffma2(h8[i], w2[1][i], a1);
                a2 = ffma2(h8[i], w2[2][i], a2);
                a3 = ffma2(h8[i], w2[3][i], a3);
            }
            float2 f0 = unpk(a0), f1 = unpk(a1), f2 = unpk(a2), f3 = unpk(a3);
            sA0 = fmaf(m0, xqA, f0.x + f0.y);
            sA1 = fmaf(m1, xqA, f1.x + f1.y);
            sA2 = fmaf(m2, xqA, f2.x + f2.y);
            sA3 = fmaf(m3, xqA, f3.x + f3.y);
        }
        // ---- row B partial dots ----
        float sB0, sB1, sB2, sB3;
        {
            ull h8[8];
            unsigned ha = shb + buf * 640 + 320 + q * 80;
            lds_v2u64(h8[0], h8[1], ha);
            lds_v2u64(h8[2], h8[3], ha + 16);
            lds_v2u64(h8[4], h8[5], ha + 32);
            lds_v2u64(h8[6], h8[7], ha + 48);
            ull a0 = 0ull, a1 = 0ull, a2 = 0ull, a3 = 0ull;
#pragma unroll
            for (int i = 0; i < 8; i++) {
                a0 = ffma2(h8[i], w2[0][i], a0);
                a1 = ffma2(h8[i], w2[1][i], a1);
                a2 = ffma2(h8[i], w2[2][i], a2);
                a3 = ffma2(h8[i], w2[3][i], a3);
            }
            float2 f0 = unpk(a0), f1 = unpk(a1), f2 = unpk(a2), f3 = unpk(a3);
            sB0 = fmaf(m0, xqB, f0.x + f0.y);
            sB1 = fmaf(m1, xqB, f1.x + f1.y);
            sB2 = fmaf(m2, xqB, f2.x + f2.y);
            sB3 = fmaf(m3, xqB, f3.x + f3.y);
        }

        // quad butterflies (both rows interleaved for latency overlap)
        sA0 += __shfl_xor_sync(FULL, sA0, 1);
        sA1 += __shfl_xor_sync(FULL, sA1, 1);
        sA2 += __shfl_xor_sync(FULL, sA2, 1);
        sA3 += __shfl_xor_sync(FULL, sA3, 1);
        sB0 += __shfl_xor_sync(FULL, sB0, 1);
        sB1 += __shfl_xor_sync(FULL, sB1, 1);
        sB2 += __shfl_xor_sync(FULL, sB2, 1);
        sB3 += __shfl_xor_sync(FULL, sB3, 1);
        sA0 += __shfl_xor_sync(FULL, sA0, 2);
        sA1 += __shfl_xor_sync(FULL, sA1, 2);
        sA2 += __shfl_xor_sync(FULL, sA2, 2);
        sA3 += __shfl_xor_sync(FULL, sA3, 2);
        sB0 += __shfl_xor_sync(FULL, sB0, 2);
        sB1 += __shfl_xor_sync(FULL, sB1, 2);
        sB2 += __shfl_xor_sync(FULL, sB2, 2);
        sB3 += __shfl_xor_sync(FULL, sB3, 2);

        // activations (redundant across quad; bit-identical)
        float ivA = siga(sA0), fvA = siga(sA1), gvA = tanha(sA2), ovA = siga(sA3);
        cstA = fmaf(fvA, cstA, ivA * gvA);
        float hA = ovA * tanha(cstA);
        float ivB = siga(sB0), fvB = siga(sB1), gvB = tanha(sB2), ovB = siga(sB3);
        cstB = fmaf(fvB, cstB, ivB * gvB);
        float hB = ovB * tanha(cstB);

        buf ^= 1;
        if (q == 0) {
            sh_h[buf][0][wc] = hA;
            sh_h[buf][1][wc] = hB;
            houtA[(size_t)tt * Hdim + c] = hA;
            houtB[(size_t)tt * Hdim + c] = hB;
        }
        __syncthreads();
        tt += step;
    }
}

// ------------------------------------------------------------------
// Kernel 3: emissions[token][k] = b_tag[k] + [h_f;h_b] . W_tag[k]
// ------------------------------------------------------------------
__global__ void __launch_bounds__(128) emissions_kernel(
    const float* __restrict__ W_tag, const float* __restrict__ b_tag)
{
    __shared__ __align__(16) float hs[128][68];
    __shared__ __align__(16) float Ws[10 * 128];
    const int tid = threadIdx.x;
    const int tok0 = blockIdx.x * 128;

    for (int i = tid; i < 10 * 128; i += 128) Ws[i] = W_tag[i];

    float acc[10];
#pragma unroll
    for (int k = 0; k < 10; k++) acc[k] = 0.f;

    const float* hf = g_h;
    const float* hb = g_h + (size_t)TOKENS * Hdim;

#pragma unroll
    for (int pass = 0; pass < 2; pass++) {
        const float* src = pass ? hb : hf;
        __syncthreads();
        for (int i = tid; i < 128 * 16; i += 128) {
            int row = i >> 4, cc = i & 15;
            float4 v = ((const float4*)(src + (size_t)(tok0 + row) * 64))[cc];
            *(float4*)&hs[row][cc * 4] = v;
        }
        __syncthreads();

        const float4* hrow = (const float4*)&hs[tid][0];
        const float4* W4 = (const float4*)(Ws + pass * 64);
#pragma unroll
        for (int cc = 0; cc < 16; cc++) {
            float4 h = hrow[cc];
#pragma unroll
            for (int k = 0; k < 10; k++) {
                float4 w = W4[k * 32 + cc];
                acc[k] = fmaf(h.x, w.x, fmaf(h.y, w.y, fmaf(h.z, w.z, fmaf(h.w, w.w, acc[k]))));
            }
        }
    }

#pragma unroll
    for (int k = 0; k < 10; k++)
        g_em[(size_t)(tok0 + tid) * Ktags + k] = acc[k] + b_tag[k];
}

// ------------------------------------------------------------------
// Kernel 4: CRF log-likelihood — TWO sequences per warp (width-16
// shuffles), 4-deep em prefetch ring. grid=32, block=128.
// ------------------------------------------------------------------
__global__ void __launch_bounds__(128) crf_kernel(
    const int* __restrict__ tags, const float* __restrict__ trans,
    const float* __restrict__ startv, const float* __restrict__ endv)
{
    const int warp = threadIdx.x >> 5;
    const int lane = threadIdx.x & 31;
    const int sub  = lane >> 4;         // 0/1: sequence within warp
    const int l    = lane & 15;
    const int b = blockIdx.x * 8 + warp * 2 + sub;
    const int* tg = tags + (size_t)b * Tlen;
    const unsigned FULL = 0xffffffffu;

    // ---- numerator (16 lanes per sequence) ----
    float num = 0.f;
    for (int t = l; t < Tlen; t += 16) {
        int tag = tg[t];
        num += g_em[(size_t)(b * Tlen + t) * Ktags + tag];
        if (t > 0) num += trans[tg[t - 1] * Ktags + tag];
    }
#pragma unroll
    for (int o = 8; o; o >>= 1) num += __shfl_xor_sync(FULL, num, o, 16);
    num += startv[tg[0]] + endv[tg[Tlen - 1]];

    // ---- denominator (exp-domain forward recurrence, width-16) ----
    const int jj = (l < Ktags) ? l : 0;
    float tre[Ktags];
#pragma unroll
    for (int i = 0; i < Ktags; i++) tre[i] = __expf(trans[i * Ktags + jj]);

    const float* emrow = g_em + (size_t)b * Tlen * Ktags;
    float ea = __expf(startv[jj] + emrow[jj]);
    if (l >= Ktags) ea = 0.f;
    float base = 0.f;

    float embuf[4];
#pragma unroll
    for (int u = 0; u < 4; u++) embuf[u] = emrow[(size_t)(1 + u) * Ktags + jj];

    for (int t = 1; t < Tlen; t++) {
        float em_c = embuf[(t - 1) & 3];
        if (t + 4 < Tlen) embuf[(t - 1) & 3] = emrow[(size_t)(t + 4) * Ktags + jj];
        float s0 = 0.f, s1 = 0.f;
#pragma unroll
        for (int i = 0; i < Ktags; i += 2) {
            s0 = fmaf(__shfl_sync(FULL, ea, i,     16), tre[i],     s0);
            s1 = fmaf(__shfl_sync(FULL, ea, i + 1, 16), tre[i + 1], s1);
        }
        ea = (s0 + s1) * __expf(em_c);
        if ((t & 7) == 7) {
            float r = (l < Ktags) ? ea : 0.f;
#pragma unroll
            for (int o = 8; o; o >>= 1) r += __shfl_xor_sync(FULL, r, o, 16);
            base += __logf(r);
            ea = __fdividef(ea, r);
        }
    }
    float r = (l < Ktags) ? ea * __expf(endv[jj]) : 0.f;
#pragma unroll
    for (int o = 8; o; o >>= 1) r += __shfl_xor_sync(FULL, r, o, 16);
    float den = base + __logf(r);

    if (l == 0) g_llh[b] = num - den;
}

// ------------------------------------------------------------------
// Kernel 5: final reduction -> -mean(llh)
// ------------------------------------------------------------------
__global__ void __launch_bounds__(256) reduce_kernel(float* __restrict__ out)
{
    const int tid = threadIdx.x;
    float v = g_llh[tid];
#pragma unroll
    for (int o = 16; o; o >>= 1) v += __shfl_xor_sync(0xffffffffu, v, o);
    __shared__ float ws[8];
    if ((tid & 31) == 0) ws[tid >> 5] = v;
    __syncthreads();
    if (tid == 0) {
        float s = 0.f;
#pragma unroll
        for (int i = 0; i < 8; i++) s += ws[i];
        out[0] = -s / (float)Bsz;
    }
}

// ------------------------------------------------------------------
extern "C" void kernel_launch(void* const* d_in, const int* in_sizes, int n_in,
                              void* d_out, int out_size)
{
    const int*   syll_in  = (const int*)  d_in[0];
    const int*   word_in  = (const int*)  d_in[1];
    const int*   tags     = (const int*)  d_in[2];
    // d_in[3] = mask (all true) -> ignored
    const float* syll_emb = (const float*)d_in[4];
    const float* word_emb = (const float*)d_in[5];
    const float* w_ih_f   = (const float*)d_in[6];
    const float* w_hh_f   = (const float*)d_in[7];
    const float* b_ih_f   = (const float*)d_in[8];
    const float* b_hh_f   = (const float*)d_in[9];
    const float* w_ih_b   = (const float*)d_in[10];
    const float* w_hh_b   = (const float*)d_in[11];
    const float* b_ih_b   = (const float*)d_in[12];
    const float* b_hh_b   = (const float*)d_in[13];
    const float* W_tag    = (const float*)d_in[14];
    const float* b_tag    = (const float*)d_in[15];
    const float* crf_start= (const float*)d_in[16];
    const float* crf_end  = (const float*)d_in[17];
    const float* crf_trans= (const float*)d_in[18];
    float* out = (float*)d_out;

    float* Ps; cudaGetSymbolAddress((void**)&Ps, g_Ps);
    float* Pw; cudaGetSymbolAddress((void**)&Pw, g_Pw);

    // 1) pre-project embedding tables (biases folded into syllable table)
    proj_kernel<SYLL_D, 0, true><<<SYLL_V / 16, 512>>>(
        syll_emb, w_ih_f, w_ih_b, b_ih_f, b_hh_f, b_ih_b, b_hh_b, Ps);
    proj_kernel<WORD_D, SYLL_D, false><<<WORD_V / 16, 512>>>(
        word_emb, w_ih_f, w_ih_b, b_ih_f, b_hh_f, b_ih_b, b_hh_b, Pw);

    // 1.5) no-op to keep the ncu sampling slot on lstm_kernel
    dummy_kernel<<<1, 32>>>();

    // 2) bidirectional LSTM recurrence (quad-split, 2 rows/block, 1 wave)
    lstm_kernel<<<256, 256>>>(syll_in, word_in, w_hh_f, w_hh_b);

    // 3) emissions
    emissions_kernel<<<TOKENS / 128, 128>>>(W_tag, b_tag);

    // 4) CRF per-batch log-likelihood (2 sequences per warp)
    crf_kernel<<<Bsz / 8, 128>>>(tags, crf_trans, crf_start, crf_end);

    // 5) -mean
    reduce_kernel<<<1, 256>>>(out);
}